// round 7
// baseline (speedup 1.0000x reference)
#include <cuda_runtime.h>
#include <cuda_bf16.h>
#include <cstdint>

#define Dv 512
#define Rv 64
#define TM 128
#define NTHREADS 256

// ---------------------------------------------------------------------------
// Device scratch
// ---------------------------------------------------------------------------
__device__ float g_G0p[8 * 4096];   // partial P^T P (8 d-slabs)
// Pre-packed bf16 hi/lo operand tiles, 128B rows, SW128-swizzled
__device__ __align__(16) __nv_bfloat16 g_Abh[8 * 64 * 64];   // chunk c: [r][kk]
__device__ __align__(16) __nv_bfloat16 g_Abl[8 * 64 * 64];
__device__ __align__(16) __nv_bfloat16 g_Vbh[4 * 128 * 64];  // n-chunk j: [n][r]
__device__ __align__(16) __nv_bfloat16 g_Vbl[4 * 128 * 64];

// ---------------------------------------------------------------------------
// Helpers
// ---------------------------------------------------------------------------
#define SWZ(o) ((o) ^ (((o) >> 3) & 0x70))

__device__ __forceinline__ uint32_t smem_to_u32(const void* p) {
    uint32_t a;
    asm("{ .reg .u64 t; cvta.to.shared.u64 t, %1; cvt.u32.u64 %0, t; }" : "=r"(a) : "l"(p));
    return a;
}
__device__ __forceinline__ void ldsm4(uint32_t* r, uint32_t addr) {
    asm volatile("ldmatrix.sync.aligned.m8n8.x4.shared.b16 {%0,%1,%2,%3}, [%4];"
                 : "=r"(r[0]), "=r"(r[1]), "=r"(r[2]), "=r"(r[3]) : "r"(addr));
}
__device__ __forceinline__ void mma16816(float* c, const uint32_t* a,
                                         uint32_t b0, uint32_t b1) {
    asm volatile("mma.sync.aligned.m16n8k16.row.col.f32.bf16.bf16.f32 "
                 "{%0,%1,%2,%3}, {%4,%5,%6,%7}, {%8,%9}, {%0,%1,%2,%3};"
                 : "+f"(c[0]), "+f"(c[1]), "+f"(c[2]), "+f"(c[3])
                 : "r"(a[0]), "r"(a[1]), "r"(a[2]), "r"(a[3]), "r"(b0), "r"(b1));
}
__device__ __forceinline__ void sts64(uint32_t a, uint32_t x, uint32_t y) {
    asm volatile("st.shared.v2.b32 [%0], {%1,%2};" :: "r"(a), "r"(x), "r"(y) : "memory");
}
__device__ __forceinline__ void cpasync16(uint32_t dst, const void* src) {
    asm volatile("cp.async.cg.shared.global [%0], [%1], 16;"
                 :: "r"(dst), "l"(src) : "memory");
}
#define CP_COMMIT() asm volatile("cp.async.commit_group;" ::: "memory")
#define CP_WAIT(N)  asm volatile("cp.async.wait_group %0;" :: "n"(N) : "memory")

// non-coherent vector global load (X traffic; default L2 policy)
#define LDG_NC(v, p) \
    asm volatile("ld.global.nc.v4.f32 {%0,%1,%2,%3}, [%4];" \
                 : "=f"((v).x), "=f"((v).y), "=f"((v).z), "=f"((v).w) : "l"(p))

__device__ __forceinline__ uint32_t cvt2(float f0, float f1) {
    uint32_t r;
    asm("cvt.rn.bf16x2.f32 %0, %1, %2;" : "=r"(r) : "f"(f1), "f"(f0));
    return r;
}
__device__ __forceinline__ float bl(uint32_t h) { return __uint_as_float(h << 16); }
__device__ __forceinline__ float bh(uint32_t h) { return __uint_as_float(h & 0xFFFF0000u); }

// ---------------------------------------------------------------------------
// Precompute 1: partial Gram G0 = P^T P over d-slab b (coalesced smem tiles)
// ---------------------------------------------------------------------------
__global__ __launch_bounds__(256) void k_gram0(const float* __restrict__ P) {
    __shared__ float sP[64 * 65];
    int b = blockIdx.x, tid = threadIdx.x;
    for (int idx = tid; idx < 4096; idx += 256) {
        int row = idx >> 6, col = idx & 63;
        sP[row * 65 + col] = P[(b * 64 + row) * 64 + col];
    }
    __syncthreads();
    int j0 = (tid >> 4) << 2, k0 = (tid & 15) << 2;
    float o[4][4] = {};
    #pragma unroll 4
    for (int d = 0; d < 64; d++) {
        float va[4], vb[4];
        #pragma unroll
        for (int a = 0; a < 4; a++) va[a] = sP[d * 65 + j0 + a];
        #pragma unroll
        for (int c = 0; c < 4; c++) vb[c] = sP[d * 65 + k0 + c];
        #pragma unroll
        for (int a = 0; a < 4; a++)
            #pragma unroll
            for (int c = 0; c < 4; c++)
                o[a][c] += va[a] * vb[c];
    }
    float* dst = g_G0p + b * 4096;
    #pragma unroll
    for (int a = 0; a < 4; a++)
        #pragma unroll
        for (int c = 0; c < 4; c++)
            dst[(j0 + a) * 64 + (k0 + c)] = o[a][c];
}

// ---------------------------------------------------------------------------
// Precompute 2: one kernel, 12 blocks.
//  blocks 0-7: triangular inverse (redundant, in-smem) + pack A chunk c=bid
//  blocks 8-11: pack V n-chunk j=bid-8 (needs only rsqrt(diag))
// ---------------------------------------------------------------------------
#define SPK_RV 0
#define SPK_GT 64          // 64*65 floats
#define SPK_SW 4224        // 64*64
#define SPK_SP 8320        // 64*65 (A path); V path uses [64, 64+128*65)
#define SPK_FLOATS 12480   // 49920 bytes

__global__ __launch_bounds__(512) void k_pack(const float* __restrict__ P) {
    extern __shared__ float sm[];
    int bid = blockIdx.x, tid = threadIdx.x, w = tid >> 5, lane = tid & 31;

    if (tid < 64) {   // rv[r] = 1/|u_r|
        float s = 0.f;
        #pragma unroll
        for (int b = 0; b < 8; b++) s += g_G0p[b * 4096 + tid * 65];
        sm[SPK_RV + tid] = rsqrtf(s);
    }

    if (bid < 8) {
        int c = bid;
        for (int idx = tid; idx < 4096; idx += 512) {
            int row = idx >> 6, col = idx & 63;
            sm[SPK_SP + row * 65 + col] = P[(c * 64 + row) * 64 + col];
        }
        __syncthreads();
        // sGT[i][j] = 2 * G[j][i]  (normalized Gram)
        for (int idx = tid; idx < 4096; idx += 512) {
            int i = idx & 63, jj = idx >> 6;
            float s = 0.f;
            #pragma unroll
            for (int b = 0; b < 8; b++) s += g_G0p[b * 4096 + jj * 64 + i];
            sm[SPK_GT + i * 65 + jj] = 2.f * s * sm[SPK_RV + i] * sm[SPK_RV + jj];
        }
        __syncthreads();
        // back-substitution: W = M^-1, 16 warps x 4 columns
        for (int k = w; k < 64; k += 16) {
            for (int i = lane; i < 64; i += 32) sm[SPK_SW + k * 64 + i] = (i == k) ? 1.f : 0.f;
            __syncwarp();
            for (int i = k - 1; i >= 0; i--) {
                float s = 0.f;
                for (int j = i + 1 + lane; j <= k; j += 32)
                    s += sm[SPK_GT + i * 65 + j] * sm[SPK_SW + k * 64 + j];
                #pragma unroll
                for (int o = 16; o; o >>= 1) s += __shfl_xor_sync(0xFFFFFFFFu, s, o);
                if (lane == 0) sm[SPK_SW + k * 64 + i] = -s;
                __syncwarp();
            }
        }
        __syncthreads();
        // W2[j][r] = 2 rv[j] W[j][r]  (into GT region, now free)
        for (int idx = tid; idx < 4096; idx += 512) {
            int j = idx >> 6, r = idx & 63;
            float v = (j < r) ? 2.f * sm[SPK_RV + j] * sm[SPK_SW + r * 64 + j]
                              : (j == r ? 2.f * sm[SPK_RV + j] : 0.f);
            sm[SPK_GT + j * 65 + r] = v;
        }
        __syncthreads();
        // A'[r][kk] = sum_j P[d=c*64+kk][j] * W2[j][r]; pack bf16 hi/lo swizzled
        int rr = tid & 63, kb = (tid >> 6) << 3;
        float acc[8] = {};
        #pragma unroll 4
        for (int j = 0; j < 64; j++) {
            float wv = sm[SPK_GT + j * 65 + rr];
            #pragma unroll
            for (int e = 0; e < 8; e++)
                acc[e] += sm[SPK_SP + (kb + e) * 65 + j] * wv;
        }
        #pragma unroll
        for (int e = 0; e < 8; e++) {
            float v = acc[e];
            __nv_bfloat16 h = __float2bfloat16_rn(v);
            float lo = v - __bfloat162float(h);
            uint32_t off = c * 8192 + SWZ((uint32_t)(rr * 128 + (kb + e) * 2));
            *(__nv_bfloat16*)((char*)g_Abh + off) = h;
            *(__nv_bfloat16*)((char*)g_Abl + off) = __float2bfloat16_rn(lo);
        }
    } else {
        int jn = bid - 8;
        for (int idx = tid; idx < 8192; idx += 512) {
            int row = idx >> 6, col = idx & 63;
            sm[64 + row * 65 + col] = P[(jn * 128 + row) * 64 + col];
        }
        __syncthreads();
        for (int idx = tid; idx < 8192; idx += 512) {
            int n = idx >> 6, r = idx & 63;
            float v = sm[64 + n * 65 + r] * sm[SPK_RV + r];
            __nv_bfloat16 h = __float2bfloat16_rn(v);
            float lo = v - __bfloat162float(h);
            uint32_t off = jn * 16384 + SWZ((uint32_t)(n * 128 + r * 2));
            *(__nv_bfloat16*)((char*)g_Vbh + off) = h;
            *(__nv_bfloat16*)((char*)g_Vbl + off) = __float2bfloat16_rn(lo);
        }
    }
}

// ---------------------------------------------------------------------------
// Main kernel. smem (96KB, 2 CTA/SM):
//   [0,     32768)  Xh/Xl bf16 chunk (phase 1)  -> V buffer j=2 (phase 2)
//   [32768, 65536)  V buffer j=0 and j=3 (hi/lo)
//   [65536, 98304)  A ping/pong 16K each        -> V buffer j=1 (hi/lo)
// ---------------------------------------------------------------------------
#define OFF_XH 0
#define OFF_XL 16384
#define OFF_VA 32768
#define OFF_A0 65536
#define OFF_A1 81920
#define SMEM_BYTES 98304

__global__ __launch_bounds__(NTHREADS, 2) void k_gemm(const float* __restrict__ x,
                                                      float* __restrict__ out,
                                                      const float* __restrict__ sldj,
                                                      float* __restrict__ outSldj) {
    extern __shared__ char smem[];
    uint32_t sb = smem_to_u32(smem);
    const uint32_t sXh = sb + OFF_XH, sXl = sb + OFF_XL;

    int tid = threadIdx.x, wid = tid >> 5, lane = tid & 31;
    int m0 = blockIdx.x * TM;
    int mw = wid << 4;

    uint32_t lrow = lane & 15;
    uint32_t lcolb = (lane >> 4) << 4;
    uint32_t xw = (lrow & 7) << 4;
    uint32_t arowb = (mw + lrow) * 128;

    // per-lane X row mapping: rows mw+2u+(lane>>4), float4 group cg
    int cg = lane & 15;
    const float* xbase = x + (size_t)(m0 + mw + (lane >> 4)) * Dv + cg * 4;

    auto issueA = [&](int c, uint32_t buf) {
        const char* srch = (const char*)g_Abh + c * 8192;
        const char* srcl = (const char*)g_Abl + c * 8192;
        for (int idx = tid; idx < 512; idx += NTHREADS) {
            cpasync16(buf + idx * 16, srch + idx * 16);
            cpasync16(buf + 8192 + idx * 16, srcl + idx * 16);
        }
    };
    auto issueV = [&](int j, uint32_t bufh, uint32_t bufl) {
        const char* srch = (const char*)g_Vbh + j * 16384;
        const char* srcl = (const char*)g_Vbl + j * 16384;
        for (int idx = tid; idx < 1024; idx += NTHREADS) {
            cpasync16(bufh + idx * 16, srch + idx * 16);
            cpasync16(bufl + idx * 16, srcl + idx * 16);
        }
    };

    // prologue: V0 + A0 in flight; X chunk 0 into registers
    issueV(0, sb + OFF_VA, sb + OFF_VA + 16384);
    issueA(0, sb + OFF_A0);
    CP_COMMIT();
    float4 xc[8];
    #pragma unroll
    for (int u = 0; u < 8; u++)
        LDG_NC(xc[u], xbase + (size_t)(2 * u) * Dv);

    float acc[8][4];
    #pragma unroll
    for (int i = 0; i < 8; i++)
        acc[i][0] = acc[i][1] = acc[i][2] = acc[i][3] = 0.f;

    // ================= Phase 1: Y = X A  (8 k-chunks of 64) =================
    #pragma unroll
    for (int c = 0; c < 8; c++) {
        CP_WAIT(0);
        __syncthreads();                 // A(c) visible; MMA(c-1) done everywhere
        if (c < 7) {
            issueA(c + 1, sb + (((c + 1) & 1) ? OFF_A1 : OFF_A0));
            CP_COMMIT();
        }
        // convert own 16 rows from registers -> Xh/Xl (SW128)
        #pragma unroll
        for (int u = 0; u < 8; u++) {
            float4 v = xc[u];
            uint32_t ru = mw + 2 * u + (lane >> 4);
            uint32_t h0 = cvt2(v.x, v.y), h1 = cvt2(v.z, v.w);
            uint32_t l0 = cvt2(v.x - bl(h0), v.y - bh(h0));
            uint32_t l1 = cvt2(v.z - bl(h1), v.w - bh(h1));
            uint32_t ad = ru * 128 + (((uint32_t)(cg * 8)) ^ ((ru & 7) << 4));
            sts64(sXh + ad, h0, h1);
            sts64(sXl + ad, l0, l1);
        }
        // prefetch next X chunk (LDGs overlap MMA below)
        if (c < 7) {
            #pragma unroll
            for (int u = 0; u < 8; u++)
                LDG_NC(xc[u], xbase + (size_t)(2 * u) * Dv + (c + 1) * 64);
        }
        __syncwarp();
        uint32_t bufAh = sb + ((c & 1) ? OFF_A1 : OFF_A0);
        uint32_t bufAl = bufAh + 8192;
        #pragma unroll
        for (int ks = 0; ks < 4; ks++) {
            uint32_t ic = (lcolb + ks * 32) ^ xw;
            uint32_t ah[4], al[4];
            ldsm4(ah, sXh + arowb + ic);
            ldsm4(al, sXl + arowb + ic);
            #pragma unroll
            for (int p = 0; p < 4; p++) {
                uint32_t ro = (lrow + p * 16) * 128;
                uint32_t bhr[4], blr[4];
                ldsm4(bhr, bufAh + ro + ic);
                ldsm4(blr, bufAl + ro + ic);
                mma16816(acc[2 * p],     ah, bhr[0], bhr[2]);
                mma16816(acc[2 * p],     ah, blr[0], blr[2]);
                mma16816(acc[2 * p],     al, bhr[0], bhr[2]);
                mma16816(acc[2 * p + 1], ah, bhr[1], bhr[3]);
                mma16816(acc[2 * p + 1], ah, blr[1], blr[3]);
                mma16816(acc[2 * p + 1], al, bhr[1], bhr[3]);
            }
        }
    }
    __syncthreads();                             // MMA(7) done: A + X regions free
    issueV(1, sb + OFF_A0, sb + OFF_A1); CP_COMMIT();
    issueV(2, sb + OFF_XH, sb + OFF_XL); CP_COMMIT();

    // ======= Y: register repack acc (C-frag) -> phase-2 A-frags (hi/lo) =====
    uint32_t yh[4][4], yl[4][4];
    #pragma unroll
    for (int kb = 0; kb < 4; kb++) {
        uint32_t h;
        h = cvt2(acc[2*kb][0],   acc[2*kb][1]);   yh[kb][0] = h;
        yl[kb][0] = cvt2(acc[2*kb][0] - bl(h),    acc[2*kb][1] - bh(h));
        h = cvt2(acc[2*kb][2],   acc[2*kb][3]);   yh[kb][1] = h;
        yl[kb][1] = cvt2(acc[2*kb][2] - bl(h),    acc[2*kb][3] - bh(h));
        h = cvt2(acc[2*kb+1][0], acc[2*kb+1][1]); yh[kb][2] = h;
        yl[kb][2] = cvt2(acc[2*kb+1][0] - bl(h),  acc[2*kb+1][1] - bh(h));
        h = cvt2(acc[2*kb+1][2], acc[2*kb+1][3]); yh[kb][3] = h;
        yl[kb][3] = cvt2(acc[2*kb+1][2] - bl(h),  acc[2*kb+1][3] - bh(h));
    }

    // ================= Phase 2: Z = Y V^T, out = X - Z  (4 n-chunks) ========
    const uint32_t vhOff[4] = {OFF_VA, OFF_A0, OFF_XH, OFF_VA};
    const uint32_t vlOff[4] = {OFF_VA + 16384, OFF_A1, OFF_XL, OFF_VA + 16384};
    #pragma unroll
    for (int j = 0; j < 4; j++) {
        if (j == 1)      { CP_WAIT(2); __syncthreads(); }
        else if (j == 2) { CP_WAIT(1); __syncthreads(); }
        else if (j == 3) { CP_WAIT(0); __syncthreads(); }
        uint32_t bufVh = sb + vhOff[j], bufVl = sb + vlOff[j];

        float z[16][4];
        #pragma unroll
        for (int i = 0; i < 16; i++)
            z[i][0] = z[i][1] = z[i][2] = z[i][3] = 0.f;

        #pragma unroll
        for (int ks = 0; ks < 4; ks++) {
            uint32_t ic = (lcolb + ks * 32) ^ xw;
            #pragma unroll
            for (int p = 0; p < 8; p++) {
                uint32_t ro = (lrow + p * 16) * 128;
                uint32_t bhr[4], blr[4];
                ldsm4(bhr, bufVh + ro + ic);
                ldsm4(blr, bufVl + ro + ic);
                mma16816(z[2 * p],     yh[ks], bhr[0], bhr[2]);
                mma16816(z[2 * p],     yh[ks], blr[0], blr[2]);
                mma16816(z[2 * p],     yl[ks], bhr[0], bhr[2]);
                mma16816(z[2 * p + 1], yh[ks], bhr[1], bhr[3]);
                mma16816(z[2 * p + 1], yh[ks], blr[1], blr[3]);
                mma16816(z[2 * p + 1], yl[ks], bhr[1], bhr[3]);
            }
        }
        if (j == 0) {    // reissue V3 into buffer A after everyone is done with V0
            __syncthreads();
            issueV(3, sb + OFF_VA, sb + OFF_VA + 16384);
            CP_COMMIT();
        }

        // epilogue: out = x - z (fragment-mapped float2; x re-read hits L2)
        int r0 = m0 + mw + (lane >> 2);
        const float* x0p = x + (size_t)r0 * Dv;
        const float* x1p = x0p + 8 * Dv;
        float* o0 = out + (size_t)r0 * Dv;
        float* o1 = o0 + 8 * Dv;
        int cbase = (j << 7) + ((lane & 3) << 1);
        #pragma unroll
        for (int nt = 0; nt < 16; nt++) {
            int cc = cbase + nt * 8;
            float2 a0 = *(const float2*)(x0p + cc);
            float2 a1 = *(const float2*)(x1p + cc);
            float2 w0 = make_float2(a0.x - z[nt][0], a0.y - z[nt][1]);
            float2 w1 = make_float2(a1.x - z[nt][2], a1.y - z[nt][3]);
            *(float2*)(o0 + cc) = w0;
            *(float2*)(o1 + cc) = w1;
        }
    }

    if (outSldj != nullptr && tid < TM) {
        outSldj[m0 + tid] = sldj[m0 + tid];
    }
}

extern "C" void kernel_launch(void* const* d_in, const int* in_sizes, int n_in,
                              void* d_out, int out_size) {
    const float* x    = (const float*)d_in[0];   // (B, D)
    const float* sldj = (const float*)d_in[1];   // (B,)
    const float* P    = (const float*)d_in[2];   // (D, R)
    int BD = in_sizes[0];
    int Bn = in_sizes[1];
    (void)n_in;
    float* out = (float*)d_out;
    float* osl = (out_size >= BD + Bn) ? (out + BD) : nullptr;

    k_gram0<<<8, 256>>>(P);
    cudaFuncSetAttribute(k_pack, cudaFuncAttributeMaxDynamicSharedMemorySize,
                         SPK_FLOATS * 4);
    k_pack<<<12, 512, SPK_FLOATS * 4>>>(P);

    cudaFuncSetAttribute(k_gemm, cudaFuncAttributeMaxDynamicSharedMemorySize, SMEM_BYTES);
    k_gemm<<<Bn / TM, NTHREADS, SMEM_BYTES>>>(x, out, sldj, osl);
}